// round 1
// baseline (speedup 1.0000x reference)
#include <cuda_runtime.h>
#include <math.h>

#define BOARD   13
#define NN      169
#define DIM     128
#define CHN     8
#define NLAYERS 8
#define NBMAX   44

// ---------------------------------------------------------------------------
// Shared memory layout (one CTA = one batch element, whole net stays in SMEM)
// ---------------------------------------------------------------------------
struct Smem {
    float h[NN * DIM];            // node states          86528 B (16B aligned rows)
    float msg[NN * DIM];          // h @ msg_w            86528 B
    float agg[2 * NBMAX * DIM];   // per-half agg tile    45056 B
    int   nbr[NN * 6];            // neighbor indices
    int   cnt[NN];                // neighbor counts
    float invdeg[NN];             // 1/deg
    float red[2 * 2 * 4 * 2];     // LN reduction: [half][buf][warp][2]
    float slog[NN];               // attention logits / exp
    float gpart[2 * DIM];
    float gvec[DIM];
    float uvec[256];
    float redall[8];
    float scal[2];                // softmax max, Z
};

__device__ __forceinline__ float gelu_f(float x) {
    return 0.5f * x * (1.0f + erff(x * 0.70710678118654752440f));
}

__device__ __forceinline__ void bar_half(int half) {
    // named barrier per 128-thread half (ids 1,2); __syncthreads uses bar 0
    asm volatile("bar.sync %0, 128;" :: "r"(half + 1) : "memory");
}

// sum of (a, b) across the 128 threads of one half
__device__ __forceinline__ float2 half_sum2(float a, float b, volatile float* red,
                                            int half, int wih, int lane, int buf) {
    #pragma unroll
    for (int o = 16; o; o >>= 1) {
        a += __shfl_xor_sync(0xffffffffu, a, o);
        b += __shfl_xor_sync(0xffffffffu, b, o);
    }
    volatile float* slot = red + (((half * 2 + buf) * 4) + wih) * 2;
    if (lane == 0) { slot[0] = a; slot[1] = b; }
    bar_half(half);
    volatile float* bp = red + ((half * 2 + buf) * 4) * 2;
    float sa = bp[0] + bp[2] + bp[4] + bp[6];
    float sb = bp[1] + bp[3] + bp[5] + bp[7];
    return make_float2(sa, sb);
}

// acc[j] += sum_k src[j*DIM+k] * W[k*DIM+d],  K = 128, with next-k prefetch
template <int NB>
__device__ __forceinline__ void accum_k128(float* acc, const float* __restrict__ W,
                                           const float* __restrict__ src, int d) {
    float w0 = W[d], w1 = W[DIM + d], w2 = W[2 * DIM + d], w3 = W[3 * DIM + d];
    #pragma unroll 2
    for (int k = 0; k < DIM; k += 4) {
        float n0 = 0.f, n1 = 0.f, n2 = 0.f, n3 = 0.f;
        if (k + 4 < DIM) {
            const float* Wn = W + (k + 4) * DIM;
            n0 = Wn[d]; n1 = Wn[DIM + d]; n2 = Wn[2 * DIM + d]; n3 = Wn[3 * DIM + d];
        }
        #pragma unroll
        for (int j = 0; j < NB; j++) {
            const float4 hv = *reinterpret_cast<const float4*>(src + j * DIM + k);
            acc[j] = fmaf(hv.x, w0, acc[j]);
            acc[j] = fmaf(hv.y, w1, acc[j]);
            acc[j] = fmaf(hv.z, w2, acc[j]);
            acc[j] = fmaf(hv.w, w3, acc[j]);
        }
        w0 = n0; w1 = n1; w2 = n2; w3 = n3;
    }
}

template <int NB>
__device__ __noinline__ void do_msg(Smem& sm, const float* __restrict__ Wm,
                                    int base, int d) {
    float acc[NB];
    #pragma unroll
    for (int j = 0; j < NB; j++) acc[j] = 0.f;
    accum_k128<NB>(acc, Wm, sm.h + base * DIM, d);
    #pragma unroll
    for (int j = 0; j < NB; j++) sm.msg[(base + j) * DIM + d] = acc[j];
}

template <int NB>
__device__ __noinline__ void do_upd(Smem& sm, const float* __restrict__ Wu,
                                    const float* __restrict__ ub,
                                    const float* __restrict__ lg,
                                    const float* __restrict__ lb,
                                    int base, int half, int d, int lane, int wih) {
    float* aggh = sm.agg + half * NBMAX * DIM;
    // gather-mean from msg into agg tile (thread owns column d)
    #pragma unroll 1
    for (int j = 0; j < NB; j++) {
        const int n = base + j;
        const int c = sm.cnt[n];
        const int* nb = sm.nbr + n * 6;
        float s = 0.f;
        for (int e = 0; e < c; e++) s += sm.msg[nb[e] * DIM + d];
        aggh[j * DIM + d] = s * sm.invdeg[n];
    }
    bar_half(half);                 // agg tile complete before matmul reads all cols

    float acc[NB];
    const float bias = ub[d];
    #pragma unroll
    for (int j = 0; j < NB; j++) acc[j] = bias;
    accum_k128<NB>(acc, Wu, sm.h + base * DIM, d);           // rows   0..127: h
    accum_k128<NB>(acc, Wu + DIM * DIM, aggh, d);            // rows 128..255: agg

    bar_half(half);                 // all matmul reads of aggh done before reuse
    #pragma unroll
    for (int j = 0; j < NB; j++) aggh[j * DIM + d] = acc[j]; // park acc (own column)

    const float g = lg[d], be = lb[d];
    #pragma unroll 1
    for (int j = 0; j < NB; j++) {  // gelu + residual + LayerNorm, one node at a time
        const int n = base + j;
        float val = gelu_f(aggh[j * DIM + d]) + sm.h[n * DIM + d];
        float2 ss = half_sum2(val, val * val, sm.red, half, wih, lane, j & 1);
        float mu  = ss.x * (1.0f / DIM);
        float var = ss.y * (1.0f / DIM) - mu * mu;
        sm.h[n * DIM + d] = (val - mu) * rsqrtf(var + 1e-5f) * g + be;
    }
}

__global__ __launch_bounds__(256, 1)
void hexgnn_kernel(const float* __restrict__ x,
                   const float* __restrict__ in_w,  const float* __restrict__ in_b,
                   const float* __restrict__ in_g,  const float* __restrict__ in_beta,
                   const float* __restrict__ msg_w, const float* __restrict__ upd_w,
                   const float* __restrict__ upd_b, const float* __restrict__ ln_g,
                   const float* __restrict__ ln_b,  const float* __restrict__ aq_w,
                   const float* __restrict__ aq_b,  const float* __restrict__ pp_w,
                   const float* __restrict__ pp_b,  const float* __restrict__ v1_w,
                   const float* __restrict__ v1_b,  const float* __restrict__ v2_w,
                   const float* __restrict__ v2_b,  const float* __restrict__ tf_w,
                   const float* __restrict__ tf_b,  float* __restrict__ out) {
    extern __shared__ char smraw[];
    Smem& sm = *reinterpret_cast<Smem*>(smraw);

    const int tid  = threadIdx.x;
    const int d    = tid & (DIM - 1);
    const int half = tid >> 7;
    const int lane = tid & 31;
    const int warp = tid >> 5;
    const int wih  = warp & 3;
    const int b    = blockIdx.x;
    const int B    = gridDim.x;

    // ---- adjacency tables (fixed hex board) ----
    if (tid < NN) {
        const int i = tid / BOARD, j = tid % BOARD;
        const int di[6] = {1, -1, 0, 0, 1, -1};
        const int dj[6] = {0, 0, 1, -1, -1, 1};
        int c = 0;
        for (int e = 0; e < 6; e++) {
            int ni = i + di[e], nj = j + dj[e];
            if (ni >= 0 && ni < BOARD && nj >= 0 && nj < BOARD)
                sm.nbr[tid * 6 + (c++)] = ni * BOARD + nj;
        }
        sm.cnt[tid] = c;
        sm.invdeg[tid] = 1.0f / (float)c;
    }
    __syncthreads();

    // ---- input embedding: h = LN(gelu(x @ in_w + in_b)) ----
    {
        const int ns = half ? 88 : 0, ne = half ? NN : 88;
        const float* xb = x + (size_t)b * CHN * NN;
        const float bias = in_b[d];
        const float gg = in_g[d], be = in_beta[d];
        for (int n = ns; n < ne; n++) {
            float a = bias;
            #pragma unroll
            for (int c = 0; c < CHN; c++) a = fmaf(xb[c * NN + n], in_w[c * DIM + d], a);
            float val = gelu_f(a);
            float2 ss = half_sum2(val, val * val, sm.red, half, wih, lane, n & 1);
            float mu  = ss.x * (1.0f / DIM);
            float var = ss.y * (1.0f / DIM) - mu * mu;
            sm.h[n * DIM + d] = (val - mu) * rsqrtf(var + 1e-5f) * gg + be;
        }
    }

    // ---- 8 GNN layers ----
    for (int l = 0; l < NLAYERS; l++) {
        __syncthreads();                       // h fully written
        const float* Wm = msg_w + l * DIM * DIM;
        if (half == 0) { do_msg<44>(sm, Wm, 0, d);  do_msg<44>(sm, Wm, 44, d); }
        else           { do_msg<44>(sm, Wm, 88, d); do_msg<37>(sm, Wm, 132, d); }
        __syncthreads();                       // msg fully written (agg gathers cross-half)
        const float* Wu = upd_w + l * 2 * DIM * DIM;
        const float* ub = upd_b + l * DIM;
        const float* lg = ln_g + l * DIM;
        const float* lb = ln_b + l * DIM;
        if (half == 0) {
            do_upd<44>(sm, Wu, ub, lg, lb, 0, half, d, lane, wih);
            do_upd<44>(sm, Wu, ub, lg, lb, 44, half, d, lane, wih);
        } else {
            do_upd<44>(sm, Wu, ub, lg, lb, 88, half, d, lane, wih);
            do_upd<37>(sm, Wu, ub, lg, lb, 132, half, d, lane, wih);
        }
    }
    __syncthreads();

    // ---- heads ----
    float* p_out = out;
    float* v_out = out + (size_t)B * NN;
    float* t_out = v_out + B;
    const float ppb = pp_b[0], aqb = aq_b[0], v2b = v2_b[0];

    // p logits and attention logits (warp per node)
    for (int n = warp; n < NN; n += 8) {
        float hp = 0.f, ha = 0.f;
        #pragma unroll
        for (int i = 0; i < 4; i++) {
            const int dd = i * 32 + lane;
            const float hv = sm.h[n * DIM + dd];
            hp = fmaf(hv, pp_w[dd], hp);
            ha = fmaf(hv, aq_w[dd], ha);
        }
        #pragma unroll
        for (int o = 16; o; o >>= 1) {
            hp += __shfl_xor_sync(0xffffffffu, hp, o);
            ha += __shfl_xor_sync(0xffffffffu, ha, o);
        }
        if (lane == 0) { p_out[(size_t)b * NN + n] = hp + ppb; sm.slog[n] = ha + aqb; }
    }
    __syncthreads();
    if (warp == 0) {                                   // softmax max
        float m = -3.4e38f;
        for (int n = lane; n < NN; n += 32) m = fmaxf(m, sm.slog[n]);
        #pragma unroll
        for (int o = 16; o; o >>= 1) m = fmaxf(m, __shfl_xor_sync(0xffffffffu, m, o));
        if (lane == 0) sm.scal[0] = m;
    }
    __syncthreads();
    if (tid < NN) sm.slog[tid] = expf(sm.slog[tid] - sm.scal[0]);
    __syncthreads();
    if (warp == 0) {                                   // softmax Z
        float z = 0.f;
        for (int n = lane; n < NN; n += 32) z += sm.slog[n];
        #pragma unroll
        for (int o = 16; o; o >>= 1) z += __shfl_xor_sync(0xffffffffu, z, o);
        if (lane == 0) sm.scal[1] = z;
    }
    __syncthreads();
    {                                                  // g = sum_n h[n] * attn[n]
        const int ns = half ? 88 : 0, ne = half ? NN : 88;
        float gp = 0.f;
        for (int n = ns; n < ne; n++) gp = fmaf(sm.h[n * DIM + d], sm.slog[n], gp);
        sm.gpart[half * DIM + d] = gp;
    }
    __syncthreads();
    if (half == 0) sm.gvec[d] = (sm.gpart[d] + sm.gpart[DIM + d]) / sm.scal[1];
    __syncthreads();
    {                                                  // v1: 256 outputs
        float u = v1_b[tid];
        #pragma unroll 4
        for (int k = 0; k < DIM; k++) u = fmaf(sm.gvec[k], v1_w[k * 256 + tid], u);
        sm.uvec[tid] = gelu_f(u);
    }
    __syncthreads();
    {                                                  // v2 reduce + tanh
        float pv = sm.uvec[tid] * v2_w[tid];
        #pragma unroll
        for (int o = 16; o; o >>= 1) pv += __shfl_xor_sync(0xffffffffu, pv, o);
        if (lane == 0) sm.redall[warp] = pv;
    }
    __syncthreads();
    if (tid == 0) {
        float sv = 0.f;
        #pragma unroll
        for (int w = 0; w < 8; w++) sv += sm.redall[w];
        v_out[b] = tanhf(sv + v2b);
    }
    if (warp < 4) {                                    // t: 4 outputs
        float tp = 0.f;
        #pragma unroll
        for (int i = 0; i < 4; i++) {
            const int dd = i * 32 + lane;
            tp = fmaf(sm.gvec[dd], tf_w[dd * 4 + warp], tp);
        }
        #pragma unroll
        for (int o = 16; o; o >>= 1) tp += __shfl_xor_sync(0xffffffffu, tp, o);
        if (lane == 0) t_out[(size_t)b * 4 + warp] = tp + tf_b[warp];
    }
}

extern "C" void kernel_launch(void* const* d_in, const int* in_sizes, int n_in,
                              void* d_out, int out_size) {
    const float* x       = (const float*)d_in[0];
    // d_in[1] = src, d_in[2] = dst: fixed hex adjacency, recomputed in-kernel
    const float* in_w    = (const float*)d_in[3];
    const float* in_b    = (const float*)d_in[4];
    const float* in_g    = (const float*)d_in[5];
    const float* in_beta = (const float*)d_in[6];
    const float* msg_w   = (const float*)d_in[7];
    const float* upd_w   = (const float*)d_in[8];
    const float* upd_b   = (const float*)d_in[9];
    const float* ln_g    = (const float*)d_in[10];
    const float* ln_b    = (const float*)d_in[11];
    const float* aq_w    = (const float*)d_in[12];
    const float* aq_b    = (const float*)d_in[13];
    const float* pp_w    = (const float*)d_in[14];
    const float* pp_b    = (const float*)d_in[15];
    const float* v1_w    = (const float*)d_in[16];
    const float* v1_b    = (const float*)d_in[17];
    const float* v2_w    = (const float*)d_in[18];
    const float* v2_b    = (const float*)d_in[19];
    const float* tf_w    = (const float*)d_in[20];
    const float* tf_b    = (const float*)d_in[21];
    float* out = (float*)d_out;

    const int B = in_sizes[0] / (CHN * NN);   // 512
    const size_t smem = sizeof(Smem);
    cudaFuncSetAttribute(hexgnn_kernel, cudaFuncAttributeMaxDynamicSharedMemorySize,
                         (int)smem);
    hexgnn_kernel<<<B, 256, smem>>>(x, in_w, in_b, in_g, in_beta, msg_w, upd_w, upd_b,
                                    ln_g, ln_b, aq_w, aq_b, pp_w, pp_b, v1_w, v1_b,
                                    v2_w, v2_b, tf_w, tf_b, out);
}

// round 2
// speedup vs baseline: 1.1595x; 1.1595x over previous
#include <cuda_runtime.h>
#include <math.h>

#define BOARD   13
#define NN      169
#define DIM     128
#define CHN     8
#define NLAYERS 8

// fused weight: Wcomb[l] = msg_w[l] @ upd_w[l][128:256,:]
__device__ float Wcomb_g[NLAYERS * DIM * DIM];

// ---------------------------------------------------------------------------
// Shared memory: one CTA = one batch element, whole net resident
// ---------------------------------------------------------------------------
struct Smem {
    float h[NN * DIM];        // node states
    float hbar[NN * DIM];     // neighbor-mean of h
    int   nbr[NN * 6];
    int   cnt[NN];
    float invdeg[NN];
    float red[8 * 2 * 2 * 2]; // [group][buf][warpInGroup][2]
    float slog[NN];
    float gpart[4 * DIM];
    float gvec[DIM];
    float uvec[256];
    float redall[8];
    float scal[2];
};

__device__ __forceinline__ float gelu_f(float x) {
    return 0.5f * x * (1.0f + erff(x * 0.70710678118654752440f));
}

__device__ __forceinline__ void bar_group(int g) {
    // 64-thread named barrier per node-tile group (ids 1..8; bar 0 = syncthreads)
    asm volatile("bar.sync %0, 64;" :: "r"(g + 1) : "memory");
}

// sum of (a,b) over the 64 threads of one group
__device__ __forceinline__ float2 group_sum2(float a, float b, volatile float* red,
                                             int g, int wig, int lane, int buf) {
    #pragma unroll
    for (int o = 16; o; o >>= 1) {
        a += __shfl_xor_sync(0xffffffffu, a, o);
        b += __shfl_xor_sync(0xffffffffu, b, o);
    }
    volatile float* slot = red + (((g * 2 + buf) * 2) + wig) * 2;
    if (lane == 0) { slot[0] = a; slot[1] = b; }
    bar_group(g);
    volatile float* bp = red + ((g * 2 + buf) * 2) * 2;
    return make_float2(bp[0] + bp[2], bp[1] + bp[3]);
}

// acc{0,1}[j] += sum_k src[j*DIM+k] * W[k*DIM + d0(+1)]  (K=128, 2 output cols)
template <int NB>
__device__ __forceinline__ void accum_k128_c2(float* acc0, float* acc1,
                                              const float* __restrict__ W,
                                              const float* src, int d0) {
    const float* Wp = W + d0;
    float2 w0 = *(const float2*)(Wp);
    float2 w1 = *(const float2*)(Wp + DIM);
    float2 w2 = *(const float2*)(Wp + 2 * DIM);
    float2 w3 = *(const float2*)(Wp + 3 * DIM);
    #pragma unroll 2
    for (int k = 0; k < DIM; k += 4) {
        float2 n0 = make_float2(0.f, 0.f), n1 = n0, n2 = n0, n3 = n0;
        if (k + 4 < DIM) {
            const float* Wn = Wp + (k + 4) * DIM;
            n0 = *(const float2*)(Wn);
            n1 = *(const float2*)(Wn + DIM);
            n2 = *(const float2*)(Wn + 2 * DIM);
            n3 = *(const float2*)(Wn + 3 * DIM);
        }
        #pragma unroll
        for (int j = 0; j < NB; j++) {
            const float4 hv = *reinterpret_cast<const float4*>(src + j * DIM + k);
            acc0[j] = fmaf(hv.x, w0.x, acc0[j]); acc1[j] = fmaf(hv.x, w0.y, acc1[j]);
            acc0[j] = fmaf(hv.y, w1.x, acc0[j]); acc1[j] = fmaf(hv.y, w1.y, acc1[j]);
            acc0[j] = fmaf(hv.z, w2.x, acc0[j]); acc1[j] = fmaf(hv.z, w2.y, acc1[j]);
            acc0[j] = fmaf(hv.w, w3.x, acc0[j]); acc1[j] = fmaf(hv.w, w3.y, acc1[j]);
        }
        w0 = n0; w1 = n1; w2 = n2; w3 = n3;
    }
}

// neighbor-mean gather: hbar[tile rows] from h (all rows), 2 cols per thread
__device__ __forceinline__ void gather_tile(Smem& sm, int base, int nb_cnt, int d0) {
    #pragma unroll 1
    for (int j = 0; j < nb_cnt; j++) {
        const int n = base + j;
        const int c = sm.cnt[n];
        const int* nb = sm.nbr + n * 6;
        float s0 = 0.f, s1 = 0.f;
        for (int e = 0; e < c; e++) {
            const float2 m = *(const float2*)(sm.h + nb[e] * DIM + d0);
            s0 += m.x; s1 += m.y;
        }
        const float id = sm.invdeg[n];
        *(float2*)(sm.hbar + n * DIM + d0) = make_float2(s0 * id, s1 * id);
    }
}

template <int NB>
__device__ __forceinline__ void upd_tile(Smem& sm, const float* __restrict__ Wu1,
                                         const float* __restrict__ Wc,
                                         const float* __restrict__ ub,
                                         const float* __restrict__ lg,
                                         const float* __restrict__ lb,
                                         int base, int g, int c, int lane, int wig) {
    const int d0 = 2 * c;
    float acc0[NB], acc1[NB];
    const float2 bias = *(const float2*)(ub + d0);
    #pragma unroll
    for (int j = 0; j < NB; j++) { acc0[j] = bias.x; acc1[j] = bias.y; }
    accum_k128_c2<NB>(acc0, acc1, Wu1, sm.h + base * DIM, d0);
    accum_k128_c2<NB>(acc0, acc1, Wc, sm.hbar + base * DIM, d0);

    const float2 gg = *(const float2*)(lg + d0);
    const float2 be = *(const float2*)(lb + d0);
    #pragma unroll 1
    for (int j = 0; j < NB; j++) {
        const int n = base + j;
        const float2 hres = *(const float2*)(sm.h + n * DIM + d0);
        const float v0 = gelu_f(acc0[j]) + hres.x;
        const float v1 = gelu_f(acc1[j]) + hres.y;
        const float2 ss = group_sum2(v0 + v1, v0 * v0 + v1 * v1, sm.red, g, wig, lane, j & 1);
        const float mu  = ss.x * (1.0f / DIM);
        const float var = ss.y * (1.0f / DIM) - mu * mu;
        const float rs  = rsqrtf(var + 1e-5f);
        *(float2*)(sm.h + n * DIM + d0) =
            make_float2((v0 - mu) * rs * gg.x + be.x, (v1 - mu) * rs * gg.y + be.y);
    }
}

template <int NB>
__device__ __forceinline__ void embed_tile(Smem& sm, const float* __restrict__ xb,
                                           const float* __restrict__ in_w,
                                           const float* __restrict__ in_b,
                                           const float* __restrict__ in_g,
                                           const float* __restrict__ in_beta,
                                           int base, int g, int c, int lane, int wig) {
    const int d0 = 2 * c;
    const float2 bias = *(const float2*)(in_b + d0);
    const float2 gg   = *(const float2*)(in_g + d0);
    const float2 be   = *(const float2*)(in_beta + d0);
    #pragma unroll 1
    for (int j = 0; j < NB; j++) {
        const int n = base + j;
        float a0 = bias.x, a1 = bias.y;
        #pragma unroll
        for (int ch = 0; ch < CHN; ch++) {
            const float xv = xb[ch * NN + n];
            const float2 w = *(const float2*)(in_w + ch * DIM + d0);
            a0 = fmaf(xv, w.x, a0);
            a1 = fmaf(xv, w.y, a1);
        }
        const float v0 = gelu_f(a0), v1 = gelu_f(a1);
        const float2 ss = group_sum2(v0 + v1, v0 * v0 + v1 * v1, sm.red, g, wig, lane, j & 1);
        const float mu  = ss.x * (1.0f / DIM);
        const float var = ss.y * (1.0f / DIM) - mu * mu;
        const float rs  = rsqrtf(var + 1e-5f);
        *(float2*)(sm.h + n * DIM + d0) =
            make_float2((v0 - mu) * rs * gg.x + be.x, (v1 - mu) * rs * gg.y + be.y);
    }
}

// prep kernel: Wcomb[l] = msg_w[l] (128x128) @ upd_w[l][128:256,:] (128x128)
__global__ void prep_wcomb(const float* __restrict__ msg_w,
                           const float* __restrict__ upd_w) {
    const int l = blockIdx.y, i = blockIdx.x, c = threadIdx.x;
    const float* M = msg_w + (l * DIM + i) * DIM;
    const float* U = upd_w + l * 2 * DIM * DIM + DIM * DIM;
    float s = 0.f;
    #pragma unroll 4
    for (int k = 0; k < DIM; k++) s = fmaf(M[k], U[k * DIM + c], s);
    Wcomb_g[(l * DIM + i) * DIM + c] = s;
}

__global__ __launch_bounds__(512, 1)
void hexgnn_kernel(const float* __restrict__ x,
                   const float* __restrict__ in_w,  const float* __restrict__ in_b,
                   const float* __restrict__ in_g,  const float* __restrict__ in_beta,
                   const float* __restrict__ upd_w, const float* __restrict__ upd_b,
                   const float* __restrict__ ln_g,  const float* __restrict__ ln_b,
                   const float* __restrict__ aq_w,  const float* __restrict__ aq_b,
                   const float* __restrict__ pp_w,  const float* __restrict__ pp_b,
                   const float* __restrict__ v1_w,  const float* __restrict__ v1_b,
                   const float* __restrict__ v2_w,  const float* __restrict__ v2_b,
                   const float* __restrict__ tf_w,  const float* __restrict__ tf_b,
                   float* __restrict__ out) {
    extern __shared__ char smraw[];
    Smem& sm = *reinterpret_cast<Smem*>(smraw);

    const int tid  = threadIdx.x;
    const int g    = tid >> 6;           // node-tile group 0..7
    const int c    = tid & 63;           // column pair index
    const int d0   = 2 * c;
    const int lane = tid & 31;
    const int warp = tid >> 5;
    const int wig  = warp & 1;           // warp within group
    const int b    = blockIdx.x;
    const int B    = gridDim.x;
    const int base = (g == 0) ? 0 : 22 + (g - 1) * 21;   // tiles: 22,21x7

    // ---- adjacency tables ----
    if (tid < NN) {
        const int i = tid / BOARD, j = tid % BOARD;
        const int di[6] = {1, -1, 0, 0, 1, -1};
        const int dj[6] = {0, 0, 1, -1, -1, 1};
        int cc = 0;
        for (int e = 0; e < 6; e++) {
            int ni = i + di[e], nj = j + dj[e];
            if (ni >= 0 && ni < BOARD && nj >= 0 && nj < BOARD)
                sm.nbr[tid * 6 + (cc++)] = ni * BOARD + nj;
        }
        sm.cnt[tid] = cc;
        sm.invdeg[tid] = 1.0f / (float)cc;
    }
    __syncthreads();

    // ---- input embedding ----
    {
        const float* xb = x + (size_t)b * CHN * NN;
        if (g == 0) embed_tile<22>(sm, xb, in_w, in_b, in_g, in_beta, base, g, c, lane, wig);
        else        embed_tile<21>(sm, xb, in_w, in_b, in_g, in_beta, base, g, c, lane, wig);
    }

    // ---- 8 GNN layers: h = LN(gelu(h@Wu1 + hbar@Wcomb + ub) + h) ----
    for (int l = 0; l < NLAYERS; l++) {
        __syncthreads();                               // all h writes visible
        gather_tile(sm, base, (g == 0) ? 22 : 21, d0); // hbar from h (cross-tile reads)
        __syncthreads();                               // gathers done before h overwritten
        const float* Wu1 = upd_w + l * 2 * DIM * DIM;
        const float* Wc  = Wcomb_g + l * DIM * DIM;
        const float* ub  = upd_b + l * DIM;
        const float* lg  = ln_g + l * DIM;
        const float* lb  = ln_b + l * DIM;
        if (g == 0) upd_tile<22>(sm, Wu1, Wc, ub, lg, lb, base, g, c, lane, wig);
        else        upd_tile<21>(sm, Wu1, Wc, ub, lg, lb, base, g, c, lane, wig);
    }
    __syncthreads();

    // ---- heads ----
    float* p_out = out;
    float* v_out = out + (size_t)B * NN;
    float* t_out = v_out + B;
    const float ppb = pp_b[0], aqb = aq_b[0], v2b = v2_b[0];

    for (int n = warp; n < NN; n += 16) {              // p + attention logits
        float hp = 0.f, ha = 0.f;
        #pragma unroll
        for (int i = 0; i < 4; i++) {
            const int dd = i * 32 + lane;
            const float hv = sm.h[n * DIM + dd];
            hp = fmaf(hv, pp_w[dd], hp);
            ha = fmaf(hv, aq_w[dd], ha);
        }
        #pragma unroll
        for (int o = 16; o; o >>= 1) {
            hp += __shfl_xor_sync(0xffffffffu, hp, o);
            ha += __shfl_xor_sync(0xffffffffu, ha, o);
        }
        if (lane == 0) { p_out[(size_t)b * NN + n] = hp + ppb; sm.slog[n] = ha + aqb; }
    }
    __syncthreads();
    if (warp == 0) {                                   // softmax max
        float m = -3.4e38f;
        for (int n = lane; n < NN; n += 32) m = fmaxf(m, sm.slog[n]);
        #pragma unroll
        for (int o = 16; o; o >>= 1) m = fmaxf(m, __shfl_xor_sync(0xffffffffu, m, o));
        if (lane == 0) sm.scal[0] = m;
    }
    __syncthreads();
    if (tid < NN) sm.slog[tid] = expf(sm.slog[tid] - sm.scal[0]);
    __syncthreads();
    if (warp == 0) {                                   // softmax Z
        float z = 0.f;
        for (int n = lane; n < NN; n += 32) z += sm.slog[n];
        #pragma unroll
        for (int o = 16; o; o >>= 1) z += __shfl_xor_sync(0xffffffffu, z, o);
        if (lane == 0) sm.scal[1] = z;
    }
    __syncthreads();
    {                                                  // g = sum_n h[n] * attn[n]
        const int q = tid >> 7, dc = tid & 127;
        const int ns = (q == 0) ? 0 : 43 + (q - 1) * 42;
        const int ne = ns + ((q == 0) ? 43 : 42);
        float gp = 0.f;
        for (int n = ns; n < ne; n++) gp = fmaf(sm.h[n * DIM + dc], sm.slog[n], gp);
        sm.gpart[q * DIM + dc] = gp;
    }
    __syncthreads();
    if (tid < DIM)
        sm.gvec[tid] = (sm.gpart[tid] + sm.gpart[DIM + tid] +
                        sm.gpart[2 * DIM + tid] + sm.gpart[3 * DIM + tid]) / sm.scal[1];
    __syncthreads();
    if (tid < 256) {                                   // v1
        float u = v1_b[tid];
        #pragma unroll 4
        for (int k = 0; k < DIM; k++) u = fmaf(sm.gvec[k], v1_w[k * 256 + tid], u);
        sm.uvec[tid] = gelu_f(u);
    }
    __syncthreads();
    if (tid < 256) {                                   // v2 reduce
        float pv = sm.uvec[tid] * v2_w[tid];
        #pragma unroll
        for (int o = 16; o; o >>= 1) pv += __shfl_xor_sync(0xffffffffu, pv, o);
        if (lane == 0) sm.redall[warp] = pv;
    }
    __syncthreads();
    if (tid == 0) {
        float sv = 0.f;
        #pragma unroll
        for (int w = 0; w < 8; w++) sv += sm.redall[w];
        v_out[b] = tanhf(sv + v2b);
    }
    if (warp < 4) {                                    // t head
        float tp = 0.f;
        #pragma unroll
        for (int i = 0; i < 4; i++) {
            const int dd = i * 32 + lane;
            tp = fmaf(sm.gvec[dd], tf_w[dd * 4 + warp], tp);
        }
        #pragma unroll
        for (int o = 16; o; o >>= 1) tp += __shfl_xor_sync(0xffffffffu, tp, o);
        if (lane == 0) t_out[(size_t)b * 4 + warp] = tp + tf_b[warp];
    }
}

extern "C" void kernel_launch(void* const* d_in, const int* in_sizes, int n_in,
                              void* d_out, int out_size) {
    const float* x       = (const float*)d_in[0];
    // d_in[1]=src, d_in[2]=dst: fixed hex adjacency, recomputed in-kernel
    const float* in_w    = (const float*)d_in[3];
    const float* in_b    = (const float*)d_in[4];
    const float* in_g    = (const float*)d_in[5];
    const float* in_beta = (const float*)d_in[6];
    const float* msg_w   = (const float*)d_in[7];
    const float* upd_w   = (const float*)d_in[8];
    const float* upd_b   = (const float*)d_in[9];
    const float* ln_g    = (const float*)d_in[10];
    const float* ln_b    = (const float*)d_in[11];
    const float* aq_w    = (const float*)d_in[12];
    const float* aq_b    = (const float*)d_in[13];
    const float* pp_w    = (const float*)d_in[14];
    const float* pp_b    = (const float*)d_in[15];
    const float* v1_w    = (const float*)d_in[16];
    const float* v1_b    = (const float*)d_in[17];
    const float* v2_w    = (const float*)d_in[18];
    const float* v2_b    = (const float*)d_in[19];
    const float* tf_w    = (const float*)d_in[20];
    const float* tf_b    = (const float*)d_in[21];
    float* out = (float*)d_out;

    const int B = in_sizes[0] / (CHN * NN);   // 512

    prep_wcomb<<<dim3(DIM, NLAYERS), DIM>>>(msg_w, upd_w);

    const size_t smem = sizeof(Smem);
    cudaFuncSetAttribute(hexgnn_kernel, cudaFuncAttributeMaxDynamicSharedMemorySize,
                         (int)smem);
    hexgnn_kernel<<<B, 512, smem>>>(x, in_w, in_b, in_g, in_beta, upd_w, upd_b,
                                    ln_g, ln_b, aq_w, aq_b, pp_w, pp_b, v1_w, v1_b,
                                    v2_w, v2_b, tf_w, tf_b, out);
}

// round 4
// speedup vs baseline: 1.4135x; 1.2191x over previous
#include <cuda_runtime.h>
#include <math.h>
#include <stdint.h>

#define BOARD   13
#define NN      169
#define DIM     128
#define CHN     8
#define NLAYERS 8
#define NBW     11          // max nodes per warp (warps 0-8: 11, warps 9-15: 10)

typedef unsigned long long ull;

// Wcomb[l] = msg_w[l] @ upd_w[l][128:256,:]
__device__ float Wcomb_g[NLAYERS * DIM * DIM];
// Wall[l][quad][d][lane] = W(kk = quad*4+lane, d); kk 0-127 = upd_w top half, 128-255 = Wcomb
__device__ float Wall_g[NLAYERS * 64 * DIM * 4];

struct Smem {
    float h[NN * DIM];        // 86528 B
    float hbar[NN * DIM];     // 86528 B
    float wbuf[2][4096];      // 2 x 16 KB weight chunks
    int   nbr[NN * 6];
    int   cnt[NN];
    float invdeg[NN];
    float slog[NN];
    float gpart[4 * DIM];
    float gvec[DIM];
    float uvec[256];
    float redall[8];
    float scal[2];
};

__device__ __forceinline__ float gelu_f(float x) {
    return 0.5f * x * (1.0f + erff(x * 0.70710678118654752440f));
}

__device__ __forceinline__ void ffma2(ull& acc, ull a, ull b) {
    asm("fma.rn.f32x2 %0, %1, %2, %0;" : "+l"(acc) : "l"(a), "l"(b));
}

__device__ __forceinline__ float pair_sum(ull a) {
    return __uint_as_float((unsigned)a) + __uint_as_float((unsigned)(a >> 32));
}

__device__ __forceinline__ void cp16(const float* smem_dst, const float* gsrc) {
    uint32_t s = (uint32_t)__cvta_generic_to_shared(smem_dst);
    asm volatile("cp.async.cg.shared.global [%0], [%1], 16;" :: "r"(s), "l"(gsrc));
}

__device__ __forceinline__ float2 warp_sum2(float a, float b) {
    #pragma unroll
    for (int o = 16; o; o >>= 1) {
        a += __shfl_xor_sync(0xffffffffu, a, o);
        b += __shfl_xor_sync(0xffffffffu, b, o);
    }
    return make_float2(a, b);
}

// prep 1: Wcomb[l] = msg_w[l] (128x128) @ upd_w[l][128:256,:]
__global__ void prep_wcomb(const float* __restrict__ msg_w,
                           const float* __restrict__ upd_w) {
    const int l = blockIdx.y, i = blockIdx.x, c = threadIdx.x;
    const float* M = msg_w + (l * DIM + i) * DIM;
    const float* U = upd_w + l * 2 * DIM * DIM + DIM * DIM;
    float s = 0.f;
    #pragma unroll 4
    for (int k = 0; k < DIM; k++) s = fmaf(M[k], U[k * DIM + c], s);
    Wcomb_g[(l * DIM + i) * DIM + c] = s;
}

// prep 2: interleave into Wall (k-quad-major per column)
__global__ void prep_wall(const float* __restrict__ upd_w) {
    const int q = blockIdx.x, l = blockIdx.y, d = threadIdx.x;
    #pragma unroll
    for (int lane = 0; lane < 4; lane++) {
        const int kk = q * 4 + lane;
        float v;
        if (kk < DIM) v = upd_w[l * 2 * DIM * DIM + kk * DIM + d];
        else          v = Wcomb_g[(l * DIM + (kk - DIM)) * DIM + d];
        Wall_g[((l * 64 + q) * DIM + d) * 4 + lane] = v;
    }
}

__global__ __launch_bounds__(512, 1)
void hexgnn_kernel(const float* __restrict__ x,
                   const float* __restrict__ in_w,  const float* __restrict__ in_b,
                   const float* __restrict__ in_g,  const float* __restrict__ in_beta,
                   const float* __restrict__ upd_b, const float* __restrict__ ln_g,
                   const float* __restrict__ ln_b,  const float* __restrict__ aq_w,
                   const float* __restrict__ aq_b,  const float* __restrict__ pp_w,
                   const float* __restrict__ pp_b,  const float* __restrict__ v1_w,
                   const float* __restrict__ v1_b,  const float* __restrict__ v2_w,
                   const float* __restrict__ v2_b,  const float* __restrict__ tf_w,
                   const float* __restrict__ tf_b,  float* __restrict__ out) {
    extern __shared__ char smraw[];
    Smem& sm = *reinterpret_cast<Smem*>(smraw);

    const int tid  = threadIdx.x;
    const int lane = tid & 31;
    const int warp = tid >> 5;
    const int d0   = lane * 4;           // 4 output columns per thread
    const int b    = blockIdx.x;
    const int B    = gridDim.x;
    // exact partition: warps 0-8 own 11 nodes, warps 9-15 own 10 (9*11+7*10=169)
    const int base = (warp < 9) ? warp * 11 : 99 + (warp - 9) * 10;
    const int ncnt = (warp < 9) ? 11 : 10;

    // row offsets; j >= ncnt clamped (GEMM regularity only — NEVER written back)
    int rowoff[NBW];
    #pragma unroll
    for (int j = 0; j < NBW; j++) {
        int n = base + j; if (n > NN - 1) n = NN - 1;
        rowoff[j] = n * DIM;
    }

    // ---- adjacency tables ----
    if (tid < NN) {
        const int i = tid / BOARD, j = tid % BOARD;
        const int di[6] = {1, -1, 0, 0, 1, -1};
        const int dj[6] = {0, 0, 1, -1, -1, 1};
        int cc = 0;
        for (int e = 0; e < 6; e++) {
            int ni = i + di[e], nj = j + dj[e];
            if (ni >= 0 && ni < BOARD && nj >= 0 && nj < BOARD)
                sm.nbr[tid * 6 + (cc++)] = ni * BOARD + nj;
        }
        sm.cnt[tid] = cc;
        sm.invdeg[tid] = 1.0f / (float)cc;
    }

    // ---- input embedding: h = LN(gelu(x @ in_w + in_b)) ----
    {
        const float* xb = x + (size_t)b * CHN * NN;
        const float4 bi4 = *(const float4*)(in_b + d0);
        const float4 gg4 = *(const float4*)(in_g + d0);
        const float4 be4 = *(const float4*)(in_beta + d0);
        #pragma unroll 1
        for (int j = 0; j < NBW; j++) {
            if (j >= ncnt) break;                     // own nodes only
            const int n = rowoff[j] >> 7;
            float a0 = bi4.x, a1 = bi4.y, a2 = bi4.z, a3 = bi4.w;
            #pragma unroll
            for (int ch = 0; ch < CHN; ch++) {
                const float xv = __ldg(xb + ch * NN + n);
                const float4 w = *(const float4*)(in_w + ch * DIM + d0);
                a0 = fmaf(xv, w.x, a0); a1 = fmaf(xv, w.y, a1);
                a2 = fmaf(xv, w.z, a2); a3 = fmaf(xv, w.w, a3);
            }
            float v0 = gelu_f(a0), v1 = gelu_f(a1), v2 = gelu_f(a2), v3 = gelu_f(a3);
            float2 ss = warp_sum2(v0 + v1 + v2 + v3,
                                  v0 * v0 + v1 * v1 + v2 * v2 + v3 * v3);
            const float mu  = ss.x * (1.0f / DIM);
            const float var = ss.y * (1.0f / DIM) - mu * mu;
            const float rs  = rsqrtf(var + 1e-5f);
            *(float4*)(sm.h + rowoff[j] + d0) = make_float4(
                (v0 - mu) * rs * gg4.x + be4.x, (v1 - mu) * rs * gg4.y + be4.y,
                (v2 - mu) * rs * gg4.z + be4.z, (v3 - mu) * rs * gg4.w + be4.w);
        }
    }

    // ---- 8 GNN layers: h = LN(gelu([h|hbar] @ Wall + ub) + h) ----
    for (int l = 0; l < NLAYERS; l++) {
        __syncthreads();                              // h complete (cross-warp gather)

        // neighbor-mean gather into hbar (own rows only)
        #pragma unroll 1
        for (int j = 0; j < NBW; j++) {
            if (j >= ncnt) break;
            const int n = rowoff[j] >> 7;
            const int c = sm.cnt[n];
            const int* nb = sm.nbr + n * 6;
            float s0 = 0.f, s1 = 0.f, s2 = 0.f, s3 = 0.f;
            for (int e = 0; e < c; e++) {
                const float4 m = *(const float4*)(sm.h + nb[e] * DIM + d0);
                s0 += m.x; s1 += m.y; s2 += m.z; s3 += m.w;
            }
            const float id = sm.invdeg[n];
            *(float4*)(sm.hbar + rowoff[j] + d0) =
                make_float4(s0 * id, s1 * id, s2 * id, s3 * id);
        }

        // accumulators: pair-partials, low word seeded with bias
        ull acc[NBW][4];
        {
            const float4 ub4 = *(const float4*)(upd_b + l * DIM + d0);
            const ull b0 = (ull)__float_as_uint(ub4.x);
            const ull b1 = (ull)__float_as_uint(ub4.y);
            const ull b2 = (ull)__float_as_uint(ub4.z);
            const ull b3 = (ull)__float_as_uint(ub4.w);
            #pragma unroll
            for (int j = 0; j < NBW; j++) {
                acc[j][0] = b0; acc[j][1] = b1; acc[j][2] = b2; acc[j][3] = b3;
            }
        }

        const float* WL = Wall_g + l * 32768;
        // prefetch chunk 0
        {
            cp16(sm.wbuf[0] + tid * 4,              WL + tid * 4);
            cp16(sm.wbuf[0] + (tid + 512) * 4,      WL + (tid + 512) * 4);
            asm volatile("cp.async.commit_group;" ::: "memory");
        }
        #pragma unroll 1
        for (int c = 0; c < 8; c++) {
            asm volatile("cp.async.wait_group 0;" ::: "memory");
            __syncthreads();                          // chunk c visible; gathers done (c=0)
            if (c < 7) {
                const float* g = WL + (c + 1) * 4096;
                float* sdst = sm.wbuf[(c + 1) & 1];
                cp16(sdst + tid * 4,         g + tid * 4);
                cp16(sdst + (tid + 512) * 4, g + (tid + 512) * 4);
                asm volatile("cp.async.commit_group;" ::: "memory");
            }
            const float* src = (c < 4) ? sm.h : sm.hbar;
            const float* srcw = src + (c & 3) * 32;   // k offset within 128
            const float* wb = sm.wbuf[c & 1];
            #pragma unroll
            for (int q = 0; q < 8; q++) {
                const float* wq = wb + q * 512 + d0 * 4;
                const ulonglong2 w0 = *(const ulonglong2*)(wq);
                const ulonglong2 w1 = *(const ulonglong2*)(wq + 4);
                const ulonglong2 w2 = *(const ulonglong2*)(wq + 8);
                const ulonglong2 w3 = *(const ulonglong2*)(wq + 12);
                #pragma unroll
                for (int j = 0; j < NBW; j++) {
                    const ulonglong2 hv =
                        *(const ulonglong2*)(srcw + rowoff[j] + q * 4);
                    ffma2(acc[j][0], hv.x, w0.x); ffma2(acc[j][0], hv.y, w0.y);
                    ffma2(acc[j][1], hv.x, w1.x); ffma2(acc[j][1], hv.y, w1.y);
                    ffma2(acc[j][2], hv.x, w2.x); ffma2(acc[j][2], hv.y, w2.y);
                    ffma2(acc[j][3], hv.x, w3.x); ffma2(acc[j][3], hv.y, w3.y);
                }
            }
        }

        // epilogue: gelu + residual + warp LayerNorm (own rows ONLY — j<ncnt)
        const float4 gg4 = *(const float4*)(ln_g + l * DIM + d0);
        const float4 be4 = *(const float4*)(ln_b + l * DIM + d0);
        #pragma unroll 1
        for (int j = 0; j < NBW; j++) {
            if (j >= ncnt) break;
            const float4 r4 = *(const float4*)(sm.h + rowoff[j] + d0);
            float v0 = gelu_f(pair_sum(acc[j][0])) + r4.x;
            float v1 = gelu_f(pair_sum(acc[j][1])) + r4.y;
            float v2 = gelu_f(pair_sum(acc[j][2])) + r4.z;
            float v3 = gelu_f(pair_sum(acc[j][3])) + r4.w;
            float2 ss = warp_sum2(v0 + v1 + v2 + v3,
                                  v0 * v0 + v1 * v1 + v2 * v2 + v3 * v3);
            const float mu  = ss.x * (1.0f / DIM);
            const float var = ss.y * (1.0f / DIM) - mu * mu;
            const float rs  = rsqrtf(var + 1e-5f);
            *(float4*)(sm.h + rowoff[j] + d0) = make_float4(
                (v0 - mu) * rs * gg4.x + be4.x, (v1 - mu) * rs * gg4.y + be4.y,
                (v2 - mu) * rs * gg4.z + be4.z, (v3 - mu) * rs * gg4.w + be4.w);
        }
    }
    __syncthreads();

    // ---- heads ----
    float* p_out = out;
    float* v_out = out + (size_t)B * NN;
    float* t_out = v_out + B;
    const float ppb = pp_b[0], aqb = aq_b[0], v2b = v2_b[0];

    for (int n = warp; n < NN; n += 16) {              // p + attention logits
        float hp = 0.f, ha = 0.f;
        #pragma unroll
        for (int i = 0; i < 4; i++) {
            const int dd = i * 32 + lane;
            const float hv = sm.h[n * DIM + dd];
            hp = fmaf(hv, pp_w[dd], hp);
            ha = fmaf(hv, aq_w[dd], ha);
        }
        #pragma unroll
        for (int o = 16; o; o >>= 1) {
            hp += __shfl_xor_sync(0xffffffffu, hp, o);
            ha += __shfl_xor_sync(0xffffffffu, ha, o);
        }
        if (lane == 0) { p_out[(size_t)b * NN + n] = hp + ppb; sm.slog[n] = ha + aqb; }
    }
    __syncthreads();
    if (warp == 0) {                                   // softmax max
        float m = -3.4e38f;
        for (int n = lane; n < NN; n += 32) m = fmaxf(m, sm.slog[n]);
        #pragma unroll
        for (int o = 16; o; o >>= 1) m = fmaxf(m, __shfl_xor_sync(0xffffffffu, m, o));
        if (lane == 0) sm.scal[0] = m;
    }
    __syncthreads();
    if (tid < NN) sm.slog[tid] = expf(sm.slog[tid] - sm.scal[0]);
    __syncthreads();
    if (warp == 0) {                                   // softmax Z
        float z = 0.f;
        for (int n = lane; n < NN; n += 32) z += sm.slog[n];
        #pragma unroll
        for (int o = 16; o; o >>= 1) z += __shfl_xor_sync(0xffffffffu, z, o);
        if (lane == 0) sm.scal[1] = z;
    }
    __syncthreads();
    {                                                  // g = sum_n h[n] * attn[n]
        const int q = tid >> 7, dc = tid & 127;
        const int ns = (q == 0) ? 0 : 43 + (q - 1) * 42;
        const int ne = ns + ((q == 0) ? 43 : 42);
        float gp = 0.f;
        for (int n = ns; n < ne; n++) gp = fmaf(sm.h[n * DIM + dc], sm.slog[n], gp);
        sm.gpart[q * DIM + dc] = gp;
    }
    __syncthreads();
    if (tid < DIM)
        sm.gvec[tid] = (sm.gpart[tid] + sm.gpart[DIM + tid] +
                        sm.gpart[2 * DIM + tid] + sm.gpart[3 * DIM + tid]) / sm.scal[1];
    __syncthreads();
    if (tid < 256) {                                   // v1
        float u = v1_b[tid];
        #pragma unroll 4
        for (int k = 0; k < DIM; k++) u = fmaf(sm.gvec[k], v1_w[k * 256 + tid], u);
        sm.uvec[tid] = gelu_f(u);
    }
    __syncthreads();
    if (tid < 256) {                                   // v2 reduce
        float pv = sm.uvec[tid] * v2_w[tid];
        #pragma unroll
        for (int o = 16; o; o >>= 1) pv += __shfl_xor_sync(0xffffffffu, pv, o);
        if (lane == 0) sm.redall[warp] = pv;
    }
    __syncthreads();
    if (tid == 0) {
        float sv = 0.f;
        #pragma unroll
        for (int w = 0; w < 8; w++) sv += sm.redall[w];
        v_out[b] = tanhf(sv + v2b);
    }
    if (warp < 4) {                                    // t head
        float tp = 0.f;
        #pragma unroll
        for (int i = 0; i < 4; i++) {
            const int dd = i * 32 + lane;
            tp = fmaf(sm.gvec[dd], tf_w[dd * 4 + warp], tp);
        }
        #pragma unroll
        for (int o = 16; o; o >>= 1) tp += __shfl_xor_sync(0xffffffffu, tp, o);
        if (lane == 0) t_out[(size_t)b * 4 + warp] = tp + tf_b[warp];
    }
}

extern "C" void kernel_launch(void* const* d_in, const int* in_sizes, int n_in,
                              void* d_out, int out_size) {
    const float* x       = (const float*)d_in[0];
    // d_in[1]=src, d_in[2]=dst: fixed hex adjacency, recomputed in-kernel
    const float* in_w    = (const float*)d_in[3];
    const float* in_b    = (const float*)d_in[4];
    const float* in_g    = (const float*)d_in[5];
    const float* in_beta = (const float*)d_in[6];
    const float* msg_w   = (const float*)d_in[7];
    const float* upd_w   = (const float*)d_in[8];
    const float* upd_b   = (const float*)d_in[9];
    const float* ln_g    = (const float*)d_in[10];
    const float* ln_b    = (const float*)d_in[11];
    const float* aq_w    = (const float*)d_in[12];
    const float* aq_b    = (const float*)d_in[13];
    const float* pp_w    = (const float*)d_in[14];
    const float* pp_b    = (const float*)d_in[15];
    const float* v1_w    = (const float*)d_in[16];
    const float* v1_b    = (const float*)d_in[17];
    const float* v2_w    = (const float*)d_in[18];
    const float* v2_b    = (const float*)d_in[19];
    const float* tf_w    = (const float*)d_in[20];
    const float* tf_b    = (const float*)d_in[21];
    float* out = (float*)d_out;

    const int B = in_sizes[0] / (CHN * NN);   // 512

    prep_wcomb<<<dim3(DIM, NLAYERS), DIM>>>(msg_w, upd_w);
    prep_wall<<<dim3(64, NLAYERS), DIM>>>(upd_w);

    const size_t smem = sizeof(Smem);
    cudaFuncSetAttribute(hexgnn_kernel, cudaFuncAttributeMaxDynamicSharedMemorySize,
                         (int)smem);
    hexgnn_kernel<<<B, 512, smem>>>(x, in_w, in_b, in_g, in_beta, upd_b,
                                    ln_g, ln_b, aq_w, aq_b, pp_w, pp_b, v1_w, v1_b,
                                    v2_w, v2_b, tf_w, tf_b, out);
}

// round 5
// speedup vs baseline: 1.7269x; 1.2217x over previous
#include <cuda_runtime.h>
#include <math.h>
#include <stdint.h>

#define BOARD   13
#define NN      169
#define DIM     128
#define CHN     8
#define NLAYERS 8
#define NBW     11          // max nodes per warp (warps 0-8: 11, warps 9-15: 10)

typedef unsigned long long ull;

// Wcomb[l] = msg_w[l] @ upd_w[l][128:256,:]
__device__ float Wcomb_g[NLAYERS * DIM * DIM];
// Wall[l][q][i][lane][4]: column (lane*4+i)'s k-quad (kk=q*4..q*4+3);
// kk 0-127 = upd_w top half, 128-255 = Wcomb. Each (q,i) segment = 512B,
// lane stride 16B -> conflict-free LDS.128.
__device__ float Wall_g[NLAYERS * 64 * DIM * 4];

struct Smem {
    float h[NN * DIM];        // 86528 B
    float hbar[NN * DIM];     // 86528 B
    float wbuf[2][4096];      // 2 x 16 KB weight chunks
    int   nbr[NN * 6];
    int   cnt[NN];
    float invdeg[NN];
    float slog[NN];
    float gpart[4 * DIM];
    float gvec[DIM];
    float uvec[256];
    float redall[8];
    float scal[2];
};

__device__ __forceinline__ float gelu_f(float x) {
    return 0.5f * x * (1.0f + erff(x * 0.70710678118654752440f));
}

__device__ __forceinline__ void ffma2(ull& acc, ull a, ull b) {
    asm("fma.rn.f32x2 %0, %1, %2, %0;" : "+l"(acc) : "l"(a), "l"(b));
}

__device__ __forceinline__ float pair_sum(ull a) {
    return __uint_as_float((unsigned)a) + __uint_as_float((unsigned)(a >> 32));
}

__device__ __forceinline__ void cp16(const float* smem_dst, const float* gsrc) {
    uint32_t s = (uint32_t)__cvta_generic_to_shared(smem_dst);
    asm volatile("cp.async.cg.shared.global [%0], [%1], 16;" :: "r"(s), "l"(gsrc));
}

__device__ __forceinline__ float2 warp_sum2(float a, float b) {
    #pragma unroll
    for (int o = 16; o; o >>= 1) {
        a += __shfl_xor_sync(0xffffffffu, a, o);
        b += __shfl_xor_sync(0xffffffffu, b, o);
    }
    return make_float2(a, b);
}

// prep 1: Wcomb[l] = msg_w[l] (128x128) @ upd_w[l][128:256,:]
__global__ void prep_wcomb(const float* __restrict__ msg_w,
                           const float* __restrict__ upd_w) {
    const int l = blockIdx.y, i = blockIdx.x, c = threadIdx.x;
    const float* M = msg_w + (l * DIM + i) * DIM;
    const float* U = upd_w + l * 2 * DIM * DIM + DIM * DIM;
    float s = 0.f;
    #pragma unroll 4
    for (int k = 0; k < DIM; k++) s = fmaf(M[k], U[k * DIM + c], s);
    Wcomb_g[(l * DIM + i) * DIM + c] = s;
}

// prep 2: interleave into Wall (segmented, conflict-free layout)
__global__ void prep_wall(const float* __restrict__ upd_w) {
    const int q = blockIdx.x, l = blockIdx.y, d = threadIdx.x;   // d = column
    const int lane = d >> 2, i = d & 3;                          // d = lane*4 + i
    #pragma unroll
    for (int kq = 0; kq < 4; kq++) {
        const int kk = q * 4 + kq;
        float v;
        if (kk < DIM) v = upd_w[l * 2 * DIM * DIM + kk * DIM + d];
        else          v = Wcomb_g[(l * DIM + (kk - DIM)) * DIM + d];
        Wall_g[((((l * 64 + q) * 4 + i) * 32) + lane) * 4 + kq] = v;
    }
}

__global__ __launch_bounds__(512, 1)
void hexgnn_kernel(const float* __restrict__ x,
                   const float* __restrict__ in_w,  const float* __restrict__ in_b,
                   const float* __restrict__ in_g,  const float* __restrict__ in_beta,
                   const float* __restrict__ upd_b, const float* __restrict__ ln_g,
                   const float* __restrict__ ln_b,  const float* __restrict__ aq_w,
                   const float* __restrict__ aq_b,  const float* __restrict__ pp_w,
                   const float* __restrict__ pp_b,  const float* __restrict__ v1_w,
                   const float* __restrict__ v1_b,  const float* __restrict__ v2_w,
                   const float* __restrict__ v2_b,  const float* __restrict__ tf_w,
                   const float* __restrict__ tf_b,  float* __restrict__ out) {
    extern __shared__ char smraw[];
    Smem& sm = *reinterpret_cast<Smem*>(smraw);

    const int tid  = threadIdx.x;
    const int lane = tid & 31;
    const int warp = tid >> 5;
    const int d0   = lane * 4;           // 4 output columns per thread
    const int b    = blockIdx.x;
    const int B    = gridDim.x;
    // exact partition: warps 0-8 own 11 nodes, warps 9-15 own 10 (9*11+7*10=169)
    const int base = (warp < 9) ? warp * 11 : 99 + (warp - 9) * 10;
    const int ncnt = (warp < 9) ? 11 : 10;

    // row offsets; j >= ncnt clamped (GEMM regularity only — NEVER written back)
    int rowoff[NBW];
    #pragma unroll
    for (int j = 0; j < NBW; j++) {
        int n = base + j; if (n > NN - 1) n = NN - 1;
        rowoff[j] = n * DIM;
    }

    // ---- adjacency tables ----
    if (tid < NN) {
        const int i = tid / BOARD, j = tid % BOARD;
        const int di[6] = {1, -1, 0, 0, 1, -1};
        const int dj[6] = {0, 0, 1, -1, -1, 1};
        int cc = 0;
        for (int e = 0; e < 6; e++) {
            int ni = i + di[e], nj = j + dj[e];
            if (ni >= 0 && ni < BOARD && nj >= 0 && nj < BOARD)
                sm.nbr[tid * 6 + (cc++)] = ni * BOARD + nj;
        }
        sm.cnt[tid] = cc;
        sm.invdeg[tid] = 1.0f / (float)cc;
    }

    // ---- input embedding: h = LN(gelu(x @ in_w + in_b)) ----
    {
        const float* xb = x + (size_t)b * CHN * NN;
        const float4 bi4 = *(const float4*)(in_b + d0);
        const float4 gg4 = *(const float4*)(in_g + d0);
        const float4 be4 = *(const float4*)(in_beta + d0);
        #pragma unroll 1
        for (int j = 0; j < NBW; j++) {
            if (j >= ncnt) break;
            const int n = rowoff[j] >> 7;
            float a0 = bi4.x, a1 = bi4.y, a2 = bi4.z, a3 = bi4.w;
            #pragma unroll
            for (int ch = 0; ch < CHN; ch++) {
                const float xv = __ldg(xb + ch * NN + n);
                const float4 w = *(const float4*)(in_w + ch * DIM + d0);
                a0 = fmaf(xv, w.x, a0); a1 = fmaf(xv, w.y, a1);
                a2 = fmaf(xv, w.z, a2); a3 = fmaf(xv, w.w, a3);
            }
            float v0 = gelu_f(a0), v1 = gelu_f(a1), v2 = gelu_f(a2), v3 = gelu_f(a3);
            float2 ss = warp_sum2(v0 + v1 + v2 + v3,
                                  v0 * v0 + v1 * v1 + v2 * v2 + v3 * v3);
            const float mu  = ss.x * (1.0f / DIM);
            const float var = ss.y * (1.0f / DIM) - mu * mu;
            const float rs  = rsqrtf(var + 1e-5f);
            *(float4*)(sm.h + rowoff[j] + d0) = make_float4(
                (v0 - mu) * rs * gg4.x + be4.x, (v1 - mu) * rs * gg4.y + be4.y,
                (v2 - mu) * rs * gg4.z + be4.z, (v3 - mu) * rs * gg4.w + be4.w);
        }
    }

    // ---- 8 GNN layers: h = LN(gelu([h|hbar] @ Wall + ub) + h) ----
    for (int l = 0; l < NLAYERS; l++) {
        __syncthreads();                              // h complete (cross-warp gather)

        // neighbor-mean gather into hbar (own rows only)
        #pragma unroll 1
        for (int j = 0; j < NBW; j++) {
            if (j >= ncnt) break;
            const int n = rowoff[j] >> 7;
            const int c = sm.cnt[n];
            const int* nb = sm.nbr + n * 6;
            float s0 = 0.f, s1 = 0.f, s2 = 0.f, s3 = 0.f;
            for (int e = 0; e < c; e++) {
                const float4 m = *(const float4*)(sm.h + nb[e] * DIM + d0);
                s0 += m.x; s1 += m.y; s2 += m.z; s3 += m.w;
            }
            const float id = sm.invdeg[n];
            *(float4*)(sm.hbar + rowoff[j] + d0) =
                make_float4(s0 * id, s1 * id, s2 * id, s3 * id);
        }
        __syncthreads();                              // hbar done before pipeline barriers

        const float* WL = Wall_g + l * 32768;
        const float4 ub4 = *(const float4*)(upd_b + l * DIM + d0);
        const float4 gg4 = *(const float4*)(ln_g + l * DIM + d0);
        const float4 be4 = *(const float4*)(ln_b + l * DIM + d0);

        // two node-half passes: slots 0-5 then 6-10(+dup) — acc fits in regs
        #pragma unroll 1
        for (int pass = 0; pass < 2; pass++) {
            const int jb = pass * 6;
            // per-pass row offsets (slot 5 of pass 1 duplicates j=10, never written)
            int ro[6];
            #pragma unroll
            for (int s = 0; s < 6; s++) {
                int j = jb + s; if (j > NBW - 1) j = NBW - 1;
                ro[s] = rowoff[j];
            }

            ull acc[6][4];
            {
                const ull b0 = (ull)__float_as_uint(ub4.x);
                const ull b1 = (ull)__float_as_uint(ub4.y);
                const ull b2 = (ull)__float_as_uint(ub4.z);
                const ull b3 = (ull)__float_as_uint(ub4.w);
                #pragma unroll
                for (int s = 0; s < 6; s++) {
                    acc[s][0] = b0; acc[s][1] = b1; acc[s][2] = b2; acc[s][3] = b3;
                }
            }

            // prefetch chunk 0
            cp16(sm.wbuf[0] + tid * 4,         WL + tid * 4);
            cp16(sm.wbuf[0] + (tid + 512) * 4, WL + (tid + 512) * 4);
            asm volatile("cp.async.commit_group;" ::: "memory");

            #pragma unroll 1
            for (int c = 0; c < 8; c++) {
                asm volatile("cp.async.wait_group 0;" ::: "memory");
                __syncthreads();                      // chunk c visible everywhere
                if (c < 7) {
                    const float* g = WL + (c + 1) * 4096;
                    float* sdst = sm.wbuf[(c + 1) & 1];
                    cp16(sdst + tid * 4,         g + tid * 4);
                    cp16(sdst + (tid + 512) * 4, g + (tid + 512) * 4);
                    asm volatile("cp.async.commit_group;" ::: "memory");
                }
                const float* src = (c < 4) ? sm.h : sm.hbar;
                const float* srcw = src + (c & 3) * 32;   // k offset within 128
                const float* wb = sm.wbuf[c & 1];
                #pragma unroll
                for (int q = 0; q < 8; q++) {
                    const float* wq = wb + q * 512 + lane * 4;
                    const ulonglong2 w0 = *(const ulonglong2*)(wq);
                    const ulonglong2 w1 = *(const ulonglong2*)(wq + 128);
                    const ulonglong2 w2 = *(const ulonglong2*)(wq + 256);
                    const ulonglong2 w3 = *(const ulonglong2*)(wq + 384);
                    #pragma unroll
                    for (int s = 0; s < 6; s++) {
                        const ulonglong2 hv =
                            *(const ulonglong2*)(srcw + ro[s] + q * 4);
                        ffma2(acc[s][0], hv.x, w0.x); ffma2(acc[s][0], hv.y, w0.y);
                        ffma2(acc[s][1], hv.x, w1.x); ffma2(acc[s][1], hv.y, w1.y);
                        ffma2(acc[s][2], hv.x, w2.x); ffma2(acc[s][2], hv.y, w2.y);
                        ffma2(acc[s][3], hv.x, w3.x); ffma2(acc[s][3], hv.y, w3.y);
                    }
                }
            }

            // epilogue: gelu + residual + warp LayerNorm (valid own slots only)
            const int jn = pass ? 5 : 6;
            #pragma unroll 1
            for (int s = 0; s < jn; s++) {
                const int j = jb + s;
                if (j >= ncnt) break;
                const float4 r4 = *(const float4*)(sm.h + ro[s] + d0);
                float v0 = gelu_f(pair_sum(acc[s][0])) + r4.x;
                float v1 = gelu_f(pair_sum(acc[s][1])) + r4.y;
                float v2 = gelu_f(pair_sum(acc[s][2])) + r4.z;
                float v3 = gelu_f(pair_sum(acc[s][3])) + r4.w;
                float2 ss = warp_sum2(v0 + v1 + v2 + v3,
                                      v0 * v0 + v1 * v1 + v2 * v2 + v3 * v3);
                const float mu  = ss.x * (1.0f / DIM);
                const float var = ss.y * (1.0f / DIM) - mu * mu;
                const float rs  = rsqrtf(var + 1e-5f);
                *(float4*)(sm.h + ro[s] + d0) = make_float4(
                    (v0 - mu) * rs * gg4.x + be4.x, (v1 - mu) * rs * gg4.y + be4.y,
                    (v2 - mu) * rs * gg4.z + be4.z, (v3 - mu) * rs * gg4.w + be4.w);
            }
        }
    }
    __syncthreads();

    // ---- heads ----
    float* p_out = out;
    float* v_out = out + (size_t)B * NN;
    float* t_out = v_out + B;
    const float ppb = pp_b[0], aqb = aq_b[0], v2b = v2_b[0];

    for (int n = warp; n < NN; n += 16) {              // p + attention logits
        float hp = 0.f, ha = 0.f;
        #pragma unroll
        for (int i = 0; i < 4; i++) {
            const int dd = i * 32 + lane;
            const float hv = sm.h[n * DIM + dd];
            hp = fmaf(hv, pp_w[dd], hp);
            ha = fmaf(hv, aq_w[dd], ha);
        }
        #pragma unroll
        for (int o = 16; o; o >>= 1) {
            hp += __shfl_xor_sync(0xffffffffu, hp, o);
            ha += __shfl_xor_sync(0xffffffffu, ha, o);
        }
        if (lane == 0) { p_out[(size_t)b * NN + n] = hp + ppb; sm.slog[n] = ha + aqb; }
    }
    __syncthreads();
    if (warp == 0) {                                   // softmax max
        float m = -3.4e38f;
        for (int n = lane; n < NN; n += 32) m = fmaxf(m, sm.slog[n]);
        #pragma unroll
        for (int o = 16; o; o >>= 1) m = fmaxf(m, __shfl_xor_sync(0xffffffffu, m, o));
        if (lane == 0) sm.scal[0] = m;
    }
    __syncthreads();
    if (tid < NN) sm.slog[tid] = expf(sm.slog[tid] - sm.scal[0]);
    __syncthreads();
    if (warp == 0) {                                   // softmax Z
        float z = 0.f;
        for (int n = lane; n < NN; n += 32) z += sm.slog[n];
        #pragma unroll
        for (int o = 16; o; o >>= 1) z += __shfl_xor_sync(0xffffffffu, z, o);
        if (lane == 0) sm.scal[1] = z;
    }
    __syncthreads();
    {                                                  // g = sum_n h[n] * attn[n]
        const int q = tid >> 7, dc = tid & 127;
        const int ns = (q == 0) ? 0 : 43 + (q - 1) * 42;
        const int ne = ns + ((q == 0) ? 43 : 42);
        float gp = 0.f;
        for (int n = ns; n < ne; n++) gp = fmaf(sm.h[n * DIM + dc], sm.slog[n], gp);
        sm.gpart[q * DIM + dc] = gp;
    }
    __syncthreads();
    if (tid < DIM)
        sm.gvec[tid] = (sm.gpart[tid] + sm.gpart[DIM + tid] +
                        sm.gpart[2 * DIM + tid] + sm.gpart[3 * DIM + tid]) / sm.scal[1];
    __syncthreads();
    if (tid < 256) {                                   // v1
        float u = v1_b[tid];
        #pragma unroll 4
        for (int k = 0; k < DIM; k++) u = fmaf(sm.gvec[k], v1_w[k * 256 + tid], u);
        sm.uvec[tid] = gelu_f(u);
    }
    __syncthreads();
    if (tid < 256) {                                   // v2 reduce
        float pv = sm.uvec[tid] * v2_w[tid];
        #pragma unroll
        for (int o = 16; o; o >>= 1) pv += __shfl_xor_sync(0xffffffffu, pv, o);
        if (lane == 0) sm.redall[warp] = pv;
    }
    __syncthreads();
    if (tid == 0) {
        float sv = 0.f;
        #pragma unroll
        for (int w = 0; w < 8; w++) sv += sm.redall[w];
        v_out[b] = tanhf(sv + v2b);
    }
    if (warp < 4) {                                    // t head
        float tp = 0.f;
        #pragma unroll
        for (int i = 0; i < 4; i++) {
            const int dd = i * 32 + lane;
            tp = fmaf(sm.gvec[dd], tf_w[dd * 4 + warp], tp);
        }
        #pragma unroll
        for (int o = 16; o; o >>= 1) tp += __shfl_xor_sync(0xffffffffu, tp, o);
        if (lane == 0) t_out[(size_t)b * 4 + warp] = tp + tf_b[warp];
    }
}

extern "C" void kernel_launch(void* const* d_in, const int* in_sizes, int n_in,
                              void* d_out, int out_size) {
    const float* x       = (const float*)d_in[0];
    // d_in[1]=src, d_in[2]=dst: fixed hex adjacency, recomputed in-kernel
    const float* in_w    = (const float*)d_in[3];
    const float* in_b    = (const float*)d_in[4];
    const float* in_g    = (const float*)d_in[5];
    const float* in_beta = (const float*)d_in[6];
    const float* msg_w   = (const float*)d_in[7];
    const float* upd_w   = (const float*)d_in[8];
    const float* upd_b   = (const float*)d_in[9];
    const float* ln_g    = (const float*)d_in[10];
    const float* ln_b    = (const float*)d_in[11];
    const float* aq_w    = (const float*)d_in[12];
    const float* aq_b    = (const float*)d_in[13];
    const float* pp_w    = (const float*)d_in[14];
    const float* pp_b    = (const float*)d_in[15];
    const float* v1_w    = (const float*)d_in[16];
    const float* v1_b    = (const float*)d_in[17];
    const float* v2_w    = (const float*)d_in[18];
    const float* v2_b    = (const float*)d_in[19];
    const float* tf_w    = (const float*)d_in[20];
    const float* tf_b    = (const float*)d_in[21];
    float* out = (float*)d_out;

    const int B = in_sizes[0] / (CHN * NN);   // 512

    prep_wcomb<<<dim3(DIM, NLAYERS), DIM>>>(msg_w, upd_w);
    prep_wall<<<dim3(64, NLAYERS), DIM>>>(upd_w);

    const size_t smem = sizeof(Smem);
    cudaFuncSetAttribute(hexgnn_kernel, cudaFuncAttributeMaxDynamicSharedMemorySize,
                         (int)smem);
    hexgnn_kernel<<<B, 512, smem>>>(x, in_w, in_b, in_g, in_beta, upd_b,
                                    ln_g, ln_b, aq_w, aq_b, pp_w, pp_b, v1_w, v1_b,
                                    v2_w, v2_b, tf_w, tf_b, out);
}

// round 6
// speedup vs baseline: 1.8428x; 1.0672x over previous
#include <cuda_runtime.h>
#include <math.h>
#include <stdint.h>

#define BOARD   13
#define NN      169
#define DIM     128
#define CHN     8
#define NLAYERS 8
#define NBW     11          // max nodes per warp (warps 0-8: 11, warps 9-15: 10)

typedef unsigned long long ull;

// Wall[l][q][i][lane][4]: column (lane*4+i)'s k-quad (kk=q*4..q*4+3);
// kk 0-127 = upd_w top half, kk 128-255 = Wcomb = msg_w[l] @ upd_w[l][128:256,:].
// Each (q,i) segment = 512B, lane stride 16B -> conflict-free LDS.128.
__device__ float Wall_g[NLAYERS * 64 * DIM * 4];

struct Smem {
    float h[NN * DIM];        // 86528 B
    float hbar[NN * DIM];     // 86528 B
    float wbuf[2][4096];      // 2 x 16 KB weight chunks
    int   nbr[NN * 6];
    int   cnt[NN];
    float invdeg[NN];
    float slog[NN];
    float gpart[4 * DIM];
    float gvec[DIM];
    float uvec[256];
    float redall[8];
    float scal[2];
};

__device__ __forceinline__ float gelu_f(float x) {
    return 0.5f * x * (1.0f + erff(x * 0.70710678118654752440f));
}

__device__ __forceinline__ void ffma2(ull& acc, ull a, ull b) {
    asm("fma.rn.f32x2 %0, %1, %2, %0;" : "+l"(acc) : "l"(a), "l"(b));
}

__device__ __forceinline__ float pair_sum(ull a) {
    return __uint_as_float((unsigned)a) + __uint_as_float((unsigned)(a >> 32));
}

__device__ __forceinline__ void cp16(const float* smem_dst, const float* gsrc) {
    uint32_t s = (uint32_t)__cvta_generic_to_shared(smem_dst);
    asm volatile("cp.async.cg.shared.global [%0], [%1], 16;" :: "r"(s), "l"(gsrc));
}

__device__ __forceinline__ float2 warp_sum2(float a, float b) {
    #pragma unroll
    for (int o = 16; o; o >>= 1) {
        a += __shfl_xor_sync(0xffffffffu, a, o);
        b += __shfl_xor_sync(0xffffffffu, b, o);
    }
    return make_float2(a, b);
}

// fused prep: build Wall directly (upd_w top half copy + on-the-fly Wcomb dot)
__global__ void prep(const float* __restrict__ msg_w,
                     const float* __restrict__ upd_w) {
    const int q = blockIdx.x, l = blockIdx.y, d = threadIdx.x;   // d = column
    const int lane = d >> 2, i = d & 3;                          // d = lane*4 + i
    const float* U2 = upd_w + l * 2 * DIM * DIM + DIM * DIM;
    #pragma unroll
    for (int kq = 0; kq < 4; kq++) {
        const int kk = q * 4 + kq;
        float v;
        if (kk < DIM) {
            v = upd_w[l * 2 * DIM * DIM + kk * DIM + d];
        } else {
            const float* M = msg_w + (l * DIM + (kk - DIM)) * DIM;
            v = 0.f;
            #pragma unroll 4
            for (int k = 0; k < DIM; k++) v = fmaf(M[k], U2[k * DIM + d], v);
        }
        Wall_g[((((l * 64 + q) * 4 + i) * 32) + lane) * 4 + kq] = v;
    }
}

// one GEMM pass over NS node-slots starting at slot JB; streams 8 weight chunks,
// prefetches preWL chunk 0 into wbuf[0] during chunk 7 (if non-null).
template <int NS, int JB>
__device__ __forceinline__ void gemm_pass(Smem& sm, const float* __restrict__ WL,
                                          const float* __restrict__ preWL,
                                          const int* rowoff, int ncnt,
                                          float4 ub4, float4 gg4, float4 be4,
                                          int tid, int lane, int d0) {
    int ro[NS];
    #pragma unroll
    for (int s = 0; s < NS; s++) {
        int j = JB + s; if (j > NBW - 1) j = NBW - 1;
        ro[s] = rowoff[j];
    }

    ull acc[NS][4];
    {
        const ull b0 = (ull)__float_as_uint(ub4.x);
        const ull b1 = (ull)__float_as_uint(ub4.y);
        const ull b2 = (ull)__float_as_uint(ub4.z);
        const ull b3 = (ull)__float_as_uint(ub4.w);
        #pragma unroll
        for (int s = 0; s < NS; s++) {
            acc[s][0] = b0; acc[s][1] = b1; acc[s][2] = b2; acc[s][3] = b3;
        }
    }

    #pragma unroll 1
    for (int c = 0; c < 8; c++) {
        asm volatile("cp.async.wait_group 0;" ::: "memory");
        __syncthreads();                      // chunk c visible; (c=0) gathers done
        if (c < 7) {
            const float* g = WL + (c + 1) * 4096;
            float* sdst = sm.wbuf[(c + 1) & 1];
            cp16(sdst + tid * 4,         g + tid * 4);
            cp16(sdst + (tid + 512) * 4, g + (tid + 512) * 4);
            asm volatile("cp.async.commit_group;" ::: "memory");
        } else if (preWL) {                   // wbuf[0] dead after c=6: prefetch ahead
            float* sdst = sm.wbuf[0];
            cp16(sdst + tid * 4,         preWL + tid * 4);
            cp16(sdst + (tid + 512) * 4, preWL + (tid + 512) * 4);
            asm volatile("cp.async.commit_group;" ::: "memory");
        }
        const float* src = (c < 4) ? sm.h : sm.hbar;
        const float* srcw = src + (c & 3) * 32;   // k offset within 128
        const float* wb = sm.wbuf[c & 1];
        #pragma unroll
        for (int q = 0; q < 8; q++) {
            const float* wq = wb + q * 512 + lane * 4;
            const ulonglong2 w0 = *(const ulonglong2*)(wq);
            const ulonglong2 w1 = *(const ulonglong2*)(wq + 128);
            const ulonglong2 w2 = *(const ulonglong2*)(wq + 256);
            const ulonglong2 w3 = *(const ulonglong2*)(wq + 384);
            #pragma unroll
            for (int s = 0; s < NS; s++) {
                const ulonglong2 hv = *(const ulonglong2*)(srcw + ro[s] + q * 4);
                ffma2(acc[s][0], hv.x, w0.x); ffma2(acc[s][0], hv.y, w0.y);
                ffma2(acc[s][1], hv.x, w1.x); ffma2(acc[s][1], hv.y, w1.y);
                ffma2(acc[s][2], hv.x, w2.x); ffma2(acc[s][2], hv.y, w2.y);
                ffma2(acc[s][3], hv.x, w3.x); ffma2(acc[s][3], hv.y, w3.y);
            }
        }
    }

    // epilogue: gelu + residual + warp LayerNorm (valid own slots only)
    #pragma unroll 1
    for (int s = 0; s < NS; s++) {
        const int j = JB + s;
        if (j >= ncnt) break;
        const float4 r4 = *(const float4*)(sm.h + ro[s] + d0);
        float v0 = gelu_f(pair_sum(acc[s][0])) + r4.x;
        float v1 = gelu_f(pair_sum(acc[s][1])) + r4.y;
        float v2 = gelu_f(pair_sum(acc[s][2])) + r4.z;
        float v3 = gelu_f(pair_sum(acc[s][3])) + r4.w;
        float2 ss = warp_sum2(v0 + v1 + v2 + v3,
                              v0 * v0 + v1 * v1 + v2 * v2 + v3 * v3);
        const float mu  = ss.x * (1.0f / DIM);
        const float var = ss.y * (1.0f / DIM) - mu * mu;
        const float rs  = rsqrtf(var + 1e-5f);
        *(float4*)(sm.h + ro[s] + d0) = make_float4(
            (v0 - mu) * rs * gg4.x + be4.x, (v1 - mu) * rs * gg4.y + be4.y,
            (v2 - mu) * rs * gg4.z + be4.z, (v3 - mu) * rs * gg4.w + be4.w);
    }
}

__global__ __launch_bounds__(512, 1)
void hexgnn_kernel(const float* __restrict__ x,
                   const float* __restrict__ in_w,  const float* __restrict__ in_b,
                   const float* __restrict__ in_g,  const float* __restrict__ in_beta,
                   const float* __restrict__ upd_b, const float* __restrict__ ln_g,
                   const float* __restrict__ ln_b,  const float* __restrict__ aq_w,
                   const float* __restrict__ aq_b,  const float* __restrict__ pp_w,
                   const float* __restrict__ pp_b,  const float* __restrict__ v1_w,
                   const float* __restrict__ v1_b,  const float* __restrict__ v2_w,
                   const float* __restrict__ v2_b,  const float* __restrict__ tf_w,
                   const float* __restrict__ tf_b,  float* __restrict__ out) {
    extern __shared__ char smraw[];
    Smem& sm = *reinterpret_cast<Smem*>(smraw);

    const int tid  = threadIdx.x;
    const int lane = tid & 31;
    const int warp = tid >> 5;
    const int d0   = lane * 4;           // 4 output columns per thread
    const int b    = blockIdx.x;
    const int B    = gridDim.x;
    // exact partition: warps 0-8 own 11 nodes, warps 9-15 own 10 (9*11+7*10=169)
    const int base = (warp < 9) ? warp * 11 : 99 + (warp - 9) * 10;
    const int ncnt = (warp < 9) ? 11 : 10;

    int rowoff[NBW];
    #pragma unroll
    for (int j = 0; j < NBW; j++) {
        int n = base + j; if (n > NN - 1) n = NN - 1;
        rowoff[j] = n * DIM;
    }

    // ---- adjacency tables ----
    if (tid < NN) {
        const int i = tid / BOARD, j = tid % BOARD;
        const int di[6] = {1, -1, 0, 0, 1, -1};
        const int dj[6] = {0, 0, 1, -1, -1, 1};
        int cc = 0;
        for (int e = 0; e < 6; e++) {
            int ni = i + di[e], nj = j + dj[e];
            if (ni >= 0 && ni < BOARD && nj >= 0 && nj < BOARD)
                sm.nbr[tid * 6 + (cc++)] = ni * BOARD + nj;
        }
        sm.cnt[tid] = cc;
        sm.invdeg[tid] = 1.0f / (float)cc;
    }

    // prefetch layer 0 chunk 0 (hidden under input embedding)
    cp16(sm.wbuf[0] + tid * 4,         Wall_g + tid * 4);
    cp16(sm.wbuf[0] + (tid + 512) * 4, Wall_g + (tid + 512) * 4);
    asm volatile("cp.async.commit_group;" ::: "memory");

    // ---- input embedding: h = LN(gelu(x @ in_w + in_b)) ----
    {
        const float* xb = x + (size_t)b * CHN * NN;
        const float4 bi4 = *(const float4*)(in_b + d0);
        const float4 gg4 = *(const float4*)(in_g + d0);
        const float4 be4 = *(const float4*)(in_beta + d0);
        #pragma unroll 1
        for (int j = 0; j < NBW; j++) {
            if (j >= ncnt) break;
            const int n = rowoff[j] >> 7;
            float a0 = bi4.x, a1 = bi4.y, a2 = bi4.z, a3 = bi4.w;
            #pragma unroll
            for (int ch = 0; ch < CHN; ch++) {
                const float xv = __ldg(xb + ch * NN + n);
                const float4 w = *(const float4*)(in_w + ch * DIM + d0);
                a0 = fmaf(xv, w.x, a0); a1 = fmaf(xv, w.y, a1);
                a2 = fmaf(xv, w.z, a2); a3 = fmaf(xv, w.w, a3);
            }
            float v0 = gelu_f(a0), v1 = gelu_f(a1), v2 = gelu_f(a2), v3 = gelu_f(a3);
            float2 ss = warp_sum2(v0 + v1 + v2 + v3,
                                  v0 * v0 + v1 * v1 + v2 * v2 + v3 * v3);
            const float mu  = ss.x * (1.0f / DIM);
            const float var = ss.y * (1.0f / DIM) - mu * mu;
            const float rs  = rsqrtf(var + 1e-5f);
            *(float4*)(sm.h + rowoff[j] + d0) = make_float4(
                (v0 - mu) * rs * gg4.x + be4.x, (v1 - mu) * rs * gg4.y + be4.y,
                (v2 - mu) * rs * gg4.z + be4.z, (v3 - mu) * rs * gg4.w + be4.w);
        }
    }

    // ---- 8 GNN layers: h = LN(gelu([h|hbar] @ Wall + ub) + h) ----
    for (int l = 0; l < NLAYERS; l++) {
        __syncthreads();                              // h complete (cross-warp gather)

        // neighbor-mean gather into hbar (own rows only)
        #pragma unroll 1
        for (int j = 0; j < NBW; j++) {
            if (j >= ncnt) break;
            const int n = rowoff[j] >> 7;
            const int c = sm.cnt[n];
            const int* nb = sm.nbr + n * 6;
            float s0 = 0.f, s1 = 0.f, s2 = 0.f, s3 = 0.f;
            for (int e = 0; e < c; e++) {
                const float4 m = *(const float4*)(sm.h + nb[e] * DIM + d0);
                s0 += m.x; s1 += m.y; s2 += m.z; s3 += m.w;
            }
            const float id = sm.invdeg[n];
            *(float4*)(sm.hbar + rowoff[j] + d0) =
                make_float4(s0 * id, s1 * id, s2 * id, s3 * id);
        }
        // no sync needed: pass-0 chunk-0 wait+sync orders all gathers before use

        const float* WL = Wall_g + l * 32768;
        const float* WLnext = (l < NLAYERS - 1) ? WL + 32768 : (const float*)0;
        const float4 ub4 = *(const float4*)(upd_b + l * DIM + d0);
        const float4 gg4 = *(const float4*)(ln_g + l * DIM + d0);
        const float4 be4 = *(const float4*)(ln_b + l * DIM + d0);

        gemm_pass<6, 0>(sm, WL, WL,     rowoff, ncnt, ub4, gg4, be4, tid, lane, d0);
        gemm_pass<5, 6>(sm, WL, WLnext, rowoff, ncnt, ub4, gg4, be4, tid, lane, d0);
    }
    __syncthreads();

    // ---- heads ----
    float* p_out = out;
    float* v_out = out + (size_t)B * NN;
    float* t_out = v_out + B;
    const float ppb = pp_b[0], aqb = aq_b[0], v2b = v2_b[0];

    for (int n = warp; n < NN; n += 16) {              // p + attention logits
        float hp = 0.f, ha = 0.f;
        #pragma unroll
        for (int i = 0; i < 4; i++) {
            const int dd = i * 32 + lane;
            const float hv = sm.h[n * DIM + dd];
            hp = fmaf(hv, pp_w[dd], hp);
            ha = fmaf(hv, aq_w[dd], ha);
        }
        #pragma unroll
        for (int o = 16; o; o >>= 1) {
            hp += __shfl_xor_sync(0xffffffffu, hp, o);
            ha += __shfl_xor_sync(0xffffffffu, ha, o);
        }
        if (lane == 0) { p_out[(size_t)b * NN + n] = hp + ppb; sm.slog[n] = ha + aqb; }
    }
    __syncthreads();
    if (warp == 0) {                                   // softmax max
        float m = -3.4e38f;
        for (int n = lane; n < NN; n += 32) m = fmaxf(m, sm.slog[n]);
        #pragma unroll
        for (int o = 16; o; o >>= 1) m = fmaxf(m, __shfl_xor_sync(0xffffffffu, m, o));
        if (lane == 0) sm.scal[0] = m;
    }
    __syncthreads();
    if (tid < NN) sm.slog[tid] = expf(sm.slog[tid] - sm.scal[0]);
    __syncthreads();
    if (warp == 0) {                                   // softmax Z
        float z = 0.f;
        for (int n = lane; n < NN; n += 32) z += sm.slog[n];
        #pragma unroll
        for (int o = 16; o; o >>= 1) z += __shfl_xor_sync(0xffffffffu, z, o);
        if (lane == 0) sm.scal[1] = z;
    }
    __syncthreads();
    {                                                  // g = sum_n h[n] * attn[n]
        const int q = tid >> 7, dc = tid & 127;
        const int ns = (q == 0) ? 0 : 43 + (q - 1) * 42;
        const int ne = ns + ((q == 0) ? 43 : 42);
        float gp = 0.f;
        for (int n = ns; n < ne; n++) gp = fmaf(sm.h[n * DIM + dc], sm.slog[n], gp);
        sm.gpart[q * DIM + dc] = gp;
    }
    __syncthreads();
    if (tid < DIM)
        sm.gvec[tid] = (sm.gpart[tid] + sm.gpart[DIM + tid] +
                        sm.gpart[2 * DIM + tid] + sm.gpart[3 * DIM + tid]) / sm.scal[1];
    __syncthreads();
    if (tid < 256) {                                   // v1
        float u = v1_b[tid];
        #pragma unroll 4
        for (int k = 0; k < DIM; k++) u = fmaf(sm.gvec[k], v1_w[k * 256 + tid], u);
        sm.uvec[tid] = gelu_f(u);
    }
    __syncthreads();
    if (tid < 256) {                                   // v2 reduce
        float pv = sm.uvec[tid] * v2_w[tid];
        #pragma unroll
        for (int o = 16; o; o >>= 1) pv += __shfl_xor_sync(0xffffffffu, pv, o);
        if (lane == 0) sm.redall[warp] = pv;
    }
    __syncthreads();
    if (tid == 0) {
        float sv = 0.f;
        #pragma unroll
        for (int w = 0; w < 8; w++) sv += sm.redall[w];
        v_out[b] = tanhf(sv + v2b);
    }
    if (warp < 4) {                                    // t head
        float tp = 0.f;
        #pragma unroll
        for (int i = 0; i < 4; i++) {
            const int dd = i * 32 + lane;
            tp = fmaf(sm.gvec[dd], tf_w[dd * 4 + warp], tp);
        }
        #pragma unroll
        for (int o = 16; o; o >>= 1) tp += __shfl_xor_sync(0xffffffffu, tp, o);
        if (lane == 0) t_out[(size_t)b * 4 + warp] = tp + tf_b[warp];
    }
}

extern "C" void kernel_launch(void* const* d_in, const int* in_sizes, int n_in,
                              void* d_out, int out_size) {
    const float* x       = (const float*)d_in[0];
    // d_in[1]=src, d_in[2]=dst: fixed hex adjacency, recomputed in-kernel
    const float* in_w    = (const float*)d_in[3];
    const float* in_b    = (const float*)d_in[4];
    const float* in_g    = (const float*)d_in[5];
    const float* in_beta = (const float*)d_in[6];
    const float* msg_w   = (const float*)d_in[7];
    const float* upd_w   = (const float*)d_in[8];
    const float* upd_b   = (const float*)d_in[9];
    const float* ln_g    = (const float*)d_in[10];
    const float* ln_b    = (const float*)d_in[11];
    const float* aq_w    = (const float*)d_in[12];
    const float* aq_b    = (const float*)d_in[13];
    const float* pp_w    = (const float*)d_in[14];
    const float* pp_b    = (const float*)d_in[15];
    const float* v1_w    = (const float*)d_in[16];
    const float* v1_b    = (const float*)d_in[17];
    const float* v2_w    = (const float*)d_in[18];
    const float* v2_b    = (const float*)d_in[19];
    const float* tf_w    = (const float*)d_in[20];
    const float* tf_b    = (const float*)d_in[21];
    float* out = (float*)d_out;

    const int B = in_sizes[0] / (CHN * NN);   // 512

    prep<<<dim3(64, NLAYERS), DIM>>>(msg_w, upd_w);

    const size_t smem = sizeof(Smem);
    cudaFuncSetAttribute(hexgnn_kernel, cudaFuncAttributeMaxDynamicSharedMemorySize,
                         (int)smem);
    hexgnn_kernel<<<B, 512, smem>>>(x, in_w, in_b, in_g, in_beta, upd_b,
                                    ln_g, ln_b, aq_w, aq_b, pp_w, pp_b, v1_w, v1_b,
                                    v2_w, v2_b, tf_w, tf_b, out);
}